// round 11
// baseline (speedup 1.0000x reference)
#include <cuda_runtime.h>
#include <cuda_bf16.h>
#include <math_constants.h>

#define BB      2
#define FF      8192
#define QQ      4096
#define NPTS    (BB * QQ)        // 8192
#define NSPLIT  64
#define FSEG    (FF / NSPLIT)    // 128
#define TILE    128              // == FSEG: single-tile blocks
#define BLK     128
#define PPT     8                // points per thread (4 f32x2 pairs)
#define NREC    11               // ulonglong2 per triangle record

typedef unsigned long long u64;

// Per-point argmin: stores ~key where key = (float_bits(d2)<<32) | fid.
// atomicMax(~key) == min(key); zero-init is the identity, so no init kernel.
// Finalize resets slots to 0 after reading (graph-replay deterministic).
// Smaller fid wins exact d2 ties = first-occurrence argmin.
__device__ u64 g_key[NPTS];   // static zero-init

// ---------------------------------------------------------------------------
// f32x2 packed helpers (sm_103a)
// ---------------------------------------------------------------------------
__device__ __forceinline__ u64 PK(float lo, float hi) {
    u64 r; asm("mov.b64 %0, {%1, %2};" : "=l"(r) : "f"(lo), "f"(hi)); return r;
}
__device__ __forceinline__ void UPK(u64 p, float& lo, float& hi) {
    asm("mov.b64 {%0, %1}, %2;" : "=f"(lo), "=f"(hi) : "l"(p));
}
__device__ __forceinline__ u64 FMA2(u64 a, u64 b, u64 c) {
    u64 d; asm("fma.rn.f32x2 %0, %1, %2, %3;" : "=l"(d) : "l"(a), "l"(b), "l"(c)); return d;
}
__device__ __forceinline__ u64 ADD2(u64 a, u64 b) {
    u64 d; asm("add.rn.f32x2 %0, %1, %2;" : "=l"(d) : "l"(a), "l"(b)); return d;
}
__device__ __forceinline__ u64 MUL2(u64 a, u64 b) {
    u64 d; asm("mul.rn.f32x2 %0, %1, %2;" : "=l"(d) : "l"(a), "l"(b)); return d;
}

__device__ __forceinline__ float clamp01(float t) {
    return fminf(fmaxf(t, 0.0f), 1.0f);
}
__device__ __forceinline__ u64 CLAMP01_2(u64 t) {
    float lo, hi; UPK(t, lo, hi);
    return PK(clamp01(lo), clamp01(hi));
}

// ---------------------------------------------------------------------------
// Exact reference arithmetic (finalize only — produces the actual outputs).
// ---------------------------------------------------------------------------
__device__ __forceinline__ float safe_div(float n, float d) {
    return n / ((d == 0.0f) ? 1.0f : d);
}

__device__ __forceinline__ void bary_uvw_exact(
    float ax, float ay, float az,
    float bx, float by, float bz,
    float cx, float cy, float cz,
    float px, float py, float pz,
    float& u, float& v, float& w)
{
    float abx = bx - ax, aby = by - ay, abz = bz - az;
    float acx = cx - ax, acy = cy - ay, acz = cz - az;
    float apx = px - ax, apy = py - ay, apz = pz - az;
    float d1 = abx * apx + aby * apy + abz * apz;
    float d2 = acx * apx + acy * apy + acz * apz;
    float bpx = px - bx, bpy = py - by, bpz = pz - bz;
    float d3 = abx * bpx + aby * bpy + abz * bpz;
    float d4 = acx * bpx + acy * bpy + acz * bpz;
    float cpx = px - cx, cpy = py - cy, cpz = pz - cz;
    float d5 = abx * cpx + aby * cpy + abz * cpz;
    float d6 = acx * cpx + acy * cpy + acz * cpz;
    float vc = d1 * d4 - d3 * d2;
    float vb = d5 * d2 - d1 * d6;
    float va = d3 * d6 - d5 * d4;

    float inv = safe_div(1.0f, va + vb + vc);
    v = vb * inv;
    w = vc * inv;

    if (va <= 0.0f && d4 >= d3 && d5 >= d6) {
        float num = d4 - d3;
        float wbc = safe_div(num, num + (d5 - d6));
        v = 1.0f - wbc; w = wbc;
    }
    if (vb <= 0.0f && d2 >= 0.0f && d6 <= 0.0f) {
        v = 0.0f; w = safe_div(d2, d2 - d6);
    }
    if (d6 >= 0.0f && d5 <= d6) { v = 0.0f; w = 1.0f; }
    if (vc <= 0.0f && d1 >= 0.0f && d3 <= 0.0f) {
        v = safe_div(d1, d1 - d3); w = 0.0f;
    }
    if (d3 >= 0.0f && d4 <= d3) { v = 1.0f; w = 0.0f; }
    if (d1 <= 0.0f && d2 <= 0.0f) { v = 0.0f; w = 0.0f; }

    u = 1.0f - v - w;
}

// ---------------------------------------------------------------------------
// Per-pair test macro (2 points packed in f32x2). Uses triangle record values
// L0..L10 from the enclosing scope. 2D-frame formulation:
// d^2 = h^2 + (inside ? 0 : min of three 2D segment distances).
// ---------------------------------------------------------------------------
#define TEST_PAIR(PX, PY, PZ, BEST0, BIDX0, BEST1, BIDX1)                     \
{                                                                             \
    u64 apx = ADD2(PX, L0.x), apy = ADD2(PY, L0.y), apz = ADD2(PZ, L1.x);     \
    u64 x = FMA2(L1.y, apx, FMA2(L2.x, apy, MUL2(L2.y, apz)));                \
    u64 y = FMA2(L3.x, apx, FMA2(L3.y, apy, MUL2(L4.x, apz)));                \
    u64 h = FMA2(L4.y, apx, FMA2(L5.x, apy, MUL2(L5.y, apz)));                \
    u64 xb = ADD2(x, L6.x);                                                   \
    float x0_, x1_, xb0_, xb1_;                                               \
    UPK(x, x0_, x1_); UPK(xb, xb0_, xb1_);                                    \
    u64 dxab = PK(fmaxf(xb0_, fminf(x0_, 0.0f)),                              \
                  fmaxf(xb1_, fminf(x1_, 0.0f)));                             \
    u64 dAB = FMA2(dxab, dxab, MUL2(y, y));                                   \
    u64 tca = CLAMP01_2(FMA2(x, L6.y, MUL2(y, L7.x)));                        \
    u64 dxc = FMA2(tca, L7.y, x);                                             \
    u64 dyc = FMA2(tca, L8.x, y);                                             \
    u64 dCA = FMA2(dxc, dxc, MUL2(dyc, dyc));                                 \
    u64 tbc = CLAMP01_2(FMA2(xb, L8.y, MUL2(y, L9.x)));                       \
    u64 dxb = FMA2(tbc, L9.y, xb);                                            \
    u64 dyb = FMA2(tbc, L8.x, y);                                             \
    u64 dBC = FMA2(dxb, dxb, MUL2(dyb, dyb));                                 \
    u64 s1 = FMA2(L10.y, x, MUL2(L7.y, y));                                   \
    u64 s2 = FMA2(L10.x, y, MUL2(L8.x, xb));                                  \
    float yy0_, yy1_, s10_, s11_, s20_, s21_;                                 \
    float dA0_, dA1_, dC0_, dC1_, dB0_, dB1_;                                 \
    UPK(y, yy0_, yy1_); UPK(s1, s10_, s11_); UPK(s2, s20_, s21_);             \
    UPK(dAB, dA0_, dA1_); UPK(dCA, dC0_, dC1_); UPK(dBC, dB0_, dB1_);         \
    float mn0_ = fminf(yy0_, fminf(s10_, s20_));                              \
    float mn1_ = fminf(yy1_, fminf(s11_, s21_));                              \
    float m0_ = (mn0_ >= 0.0f) ? 0.0f : fminf(fminf(dA0_, dC0_), dB0_);       \
    float m1_ = (mn1_ >= 0.0f) ? 0.0f : fminf(fminf(dA1_, dC1_), dB1_);       \
    u64 dist = FMA2(h, h, PK(m0_, m1_));                                      \
    float e0_, e1_; UPK(dist, e0_, e1_);                                      \
    if (e0_ < BEST0) { BEST0 = e0_; BIDX0 = fid; }                            \
    if (e1_ < BEST1) { BEST1 = e1_; BIDX1 = fid; }                            \
}

// ---------------------------------------------------------------------------
// Kernel 1: brute-force argmin search, 2D-frame, f32x2-packed, 8 pts/thread
// (4 packed pairs sharing one triangle-record load per tile row).
// grid = (NPTS/(BLK*PPT), NSPLIT) = (8, 64); one smem tile per block.
// smem record (22 packed-doubled u64 = 11 ulonglong2, 176 B/tri):
//   r0 (-ax,-ay)  r1 (-az,e1x)  r2 (e1y,e1z)  r3 (e2x,e2y)  r4 (e2z,nx)
//   r5 (ny,nz)    r6 (-b1,cs1)  r7 (cs2,-c1)  r8 (-c2,bcs1) r9 (bcs2,-bcx)
//   r10 (bcx,c2)
// ---------------------------------------------------------------------------
__global__ void __launch_bounds__(BLK, 4)
p2m_search_kernel(const float* __restrict__ tri, const float* __restrict__ pts)
{
    __shared__ ulonglong2 sT[TILE][NREC];

    const int tid = threadIdx.x;
    const int p0  = blockIdx.x * (BLK * PPT) + tid;   // 1024-aligned group:
    const int b   = p0 >> 12;                          // same batch (Q=4096)
    const float* tb = tri + (size_t)b * FF * 9;

    const u64 pxA = PK(pts[(p0          ) * 3 + 0], pts[(p0 +     BLK) * 3 + 0]);
    const u64 pyA = PK(pts[(p0          ) * 3 + 1], pts[(p0 +     BLK) * 3 + 1]);
    const u64 pzA = PK(pts[(p0          ) * 3 + 2], pts[(p0 +     BLK) * 3 + 2]);
    const u64 pxB = PK(pts[(p0 + 2 * BLK) * 3 + 0], pts[(p0 + 3 * BLK) * 3 + 0]);
    const u64 pyB = PK(pts[(p0 + 2 * BLK) * 3 + 1], pts[(p0 + 3 * BLK) * 3 + 1]);
    const u64 pzB = PK(pts[(p0 + 2 * BLK) * 3 + 2], pts[(p0 + 3 * BLK) * 3 + 2]);
    const u64 pxC = PK(pts[(p0 + 4 * BLK) * 3 + 0], pts[(p0 + 5 * BLK) * 3 + 0]);
    const u64 pyC = PK(pts[(p0 + 4 * BLK) * 3 + 1], pts[(p0 + 5 * BLK) * 3 + 1]);
    const u64 pzC = PK(pts[(p0 + 4 * BLK) * 3 + 2], pts[(p0 + 5 * BLK) * 3 + 2]);
    const u64 pxD = PK(pts[(p0 + 6 * BLK) * 3 + 0], pts[(p0 + 7 * BLK) * 3 + 0]);
    const u64 pyD = PK(pts[(p0 + 6 * BLK) * 3 + 1], pts[(p0 + 7 * BLK) * 3 + 1]);
    const u64 pzD = PK(pts[(p0 + 6 * BLK) * 3 + 2], pts[(p0 + 7 * BLK) * 3 + 2]);

    const int f0 = blockIdx.y * FSEG;

    {   // one triangle per thread: build 2D frame record
        const float* s = tb + (size_t)(f0 + tid) * 9;
        float ax = s[0], ay = s[1], az = s[2];
        float bx = s[3], by = s[4], bz = s[5];
        float cx = s[6], cy = s[7], cz = s[8];
        float abx = bx - ax, aby = by - ay, abz = bz - az;
        float acx = cx - ax, acy = cy - ay, acz = cz - az;
        float abab = fmaf(abx, abx, fmaf(aby, aby, abz * abz));
        float acac = fmaf(acx, acx, fmaf(acy, acy, acz * acz));
        float abac = fmaf(abx, acx, fmaf(aby, acy, abz * acz));

        float rs1 = rsqrtf((abab == 0.0f) ? 1.0f : abab);
        float e1x = abx * rs1, e1y = aby * rs1, e1z = abz * rs1;
        float b1  = abab * rs1;                 // |ab|
        float c1  = abac * rs1;                 // ac . e1
        float qx = fmaf(-c1, e1x, acx);         // perp part of ac
        float qy = fmaf(-c1, e1y, acy);
        float qz = fmaf(-c1, e1z, acz);
        float qq = fmaf(qx, qx, fmaf(qy, qy, qz * qz));
        float rs2 = rsqrtf((qq == 0.0f) ? 1.0f : qq);
        float e2x = qx * rs2, e2y = qy * rs2, e2z = qz * rs2;
        float c2  = qq * rs2;                   // >= 0
        float nx = fmaf(e1y, e2z, -e1z * e2y);
        float ny = fmaf(e1z, e2x, -e1x * e2z);
        float nz = fmaf(e1x, e2y, -e1y * e2x);

        float invcc = 1.0f / ((acac == 0.0f) ? 1.0f : acac);
        float cs1 = c1 * invcc, cs2 = c2 * invcc;
        float bcx = c1 - b1;                    // 2D bc = (bcx, c2)
        float bcbc = fmaf(bcx, bcx, c2 * c2);
        float invbc = 1.0f / ((bcbc == 0.0f) ? 1.0f : bcbc);
        float bcs1 = bcx * invbc, bcs2 = c2 * invbc;

        ulonglong2* r = sT[tid];
        r[0]  = make_ulonglong2(PK(-ax, -ax),   PK(-ay, -ay));
        r[1]  = make_ulonglong2(PK(-az, -az),   PK(e1x, e1x));
        r[2]  = make_ulonglong2(PK(e1y, e1y),   PK(e1z, e1z));
        r[3]  = make_ulonglong2(PK(e2x, e2x),   PK(e2y, e2y));
        r[4]  = make_ulonglong2(PK(e2z, e2z),   PK(nx, nx));
        r[5]  = make_ulonglong2(PK(ny, ny),     PK(nz, nz));
        r[6]  = make_ulonglong2(PK(-b1, -b1),   PK(cs1, cs1));
        r[7]  = make_ulonglong2(PK(cs2, cs2),   PK(-c1, -c1));
        r[8]  = make_ulonglong2(PK(-c2, -c2),   PK(bcs1, bcs1));
        r[9]  = make_ulonglong2(PK(bcs2, bcs2), PK(-bcx, -bcx));
        r[10] = make_ulonglong2(PK(bcx, bcx),   PK(c2, c2));
    }
    __syncthreads();

    float bestA0 = CUDART_INF_F, bestA1 = CUDART_INF_F;
    float bestB0 = CUDART_INF_F, bestB1 = CUDART_INF_F;
    float bestC0 = CUDART_INF_F, bestC1 = CUDART_INF_F;
    float bestD0 = CUDART_INF_F, bestD1 = CUDART_INF_F;
    int   bidxA0 = f0, bidxA1 = f0, bidxB0 = f0, bidxB1 = f0;
    int   bidxC0 = f0, bidxC1 = f0, bidxD0 = f0, bidxD1 = f0;

    #pragma unroll 1
    for (int j = 0; j < TILE; ++j) {
        const ulonglong2* r = sT[j];
        const ulonglong2 L0 = r[0], L1 = r[1], L2 = r[2], L3 = r[3];
        const ulonglong2 L4 = r[4], L5 = r[5], L6 = r[6], L7 = r[7];
        const ulonglong2 L8 = r[8], L9 = r[9], L10 = r[10];
        const int fid = f0 + j;

        TEST_PAIR(pxA, pyA, pzA, bestA0, bidxA0, bestA1, bidxA1);
        TEST_PAIR(pxB, pyB, pzB, bestB0, bidxB0, bestB1, bidxB1);
        TEST_PAIR(pxC, pyC, pzC, bestC0, bidxC0, bestC1, bidxC1);
        TEST_PAIR(pxD, pyD, pzD, bestD0, bidxD0, bestD1, bidxD1);
    }

    atomicMax(&g_key[p0          ], ~(((u64)__float_as_uint(bestA0) << 32) | (u64)(unsigned)bidxA0));
    atomicMax(&g_key[p0 +     BLK], ~(((u64)__float_as_uint(bestA1) << 32) | (u64)(unsigned)bidxA1));
    atomicMax(&g_key[p0 + 2 * BLK], ~(((u64)__float_as_uint(bestB0) << 32) | (u64)(unsigned)bidxB0));
    atomicMax(&g_key[p0 + 3 * BLK], ~(((u64)__float_as_uint(bestB1) << 32) | (u64)(unsigned)bidxB1));
    atomicMax(&g_key[p0 + 4 * BLK], ~(((u64)__float_as_uint(bestC0) << 32) | (u64)(unsigned)bidxC0));
    atomicMax(&g_key[p0 + 5 * BLK], ~(((u64)__float_as_uint(bestC1) << 32) | (u64)(unsigned)bidxC1));
    atomicMax(&g_key[p0 + 6 * BLK], ~(((u64)__float_as_uint(bestD0) << 32) | (u64)(unsigned)bidxD0));
    atomicMax(&g_key[p0 + 7 * BLK], ~(((u64)__float_as_uint(bestD1) << 32) | (u64)(unsigned)bidxD1));
}

// ---------------------------------------------------------------------------
// Kernel 2: read winning triangle (complemented key), reset slot for next
// graph replay, recompute exact reference bary, clamp, gather, write outputs.
// Output (float32): residual[8192*3] | normals[8192*3] | cmaps[8192*3] | idx[8192]
// ---------------------------------------------------------------------------
__global__ void p2m_finalize_kernel(
    const float* __restrict__ tri, const float* __restrict__ pts,
    const float* __restrict__ nrm, const float* __restrict__ cmp,
    const int*   __restrict__ faces, float* __restrict__ out)
{
    const int pid = blockIdx.x * blockDim.x + threadIdx.x;
    if (pid >= NPTS) return;

    const u64 raw = g_key[pid];
    g_key[pid] = 0ull;                         // reset for next replay
    const int bidx = (int)((~raw) & 0xFFFFFFFFull);

    const int b = pid >> 12;
    const size_t fbase = (size_t)(b * FF + bidx);

    const float px = pts[pid * 3 + 0];
    const float py = pts[pid * 3 + 1];
    const float pz = pts[pid * 3 + 2];

    const float* t = tri + fbase * 9;
    float ax = t[0], ay = t[1], az = t[2];
    float bx = t[3], by = t[4], bz = t[5];
    float cx = t[6], cy = t[7], cz = t[8];

    float u, v, w;
    bary_uvw_exact(ax, ay, az, bx, by, bz, cx, cy, cz, px, py, pz, u, v, w);

    u = fminf(fmaxf(u, 0.0f), 1.0f);
    v = fminf(fmaxf(v, 0.0f), 1.0f);
    w = fminf(fmaxf(w, 0.0f), 1.0f);

    out[pid * 3 + 0] = (u * ax + v * bx + w * cx) - px;
    out[pid * 3 + 1] = (u * ay + v * by + w * cy) - py;
    out[pid * 3 + 2] = (u * az + v * bz + w * cz) - pz;

    const float* n = nrm + fbase * 9;
    out[NPTS * 3 + pid * 3 + 0] = u * n[0] + v * n[3] + w * n[6];
    out[NPTS * 3 + pid * 3 + 1] = u * n[1] + v * n[4] + w * n[7];
    out[NPTS * 3 + pid * 3 + 2] = u * n[2] + v * n[5] + w * n[8];

    const float* cm = cmp + fbase * 9;
    out[NPTS * 6 + pid * 3 + 0] = u * cm[0] + v * cm[3] + w * cm[6];
    out[NPTS * 6 + pid * 3 + 1] = u * cm[1] + v * cm[4] + w * cm[7];
    out[NPTS * 6 + pid * 3 + 2] = u * cm[2] + v * cm[5] + w * cm[8];

    int k = (u >= v && u >= w) ? 0 : ((v >= w) ? 1 : 2);
    out[NPTS * 9 + pid] = (float)faces[fbase * 3 + k];
}

extern "C" void kernel_launch(void* const* d_in, const int* in_sizes, int n_in,
                              void* d_out, int out_size)
{
    const float* tri   = (const float*)d_in[0];   // [B,F,3,3]
    const float* pts   = (const float*)d_in[1];   // [B,Q,3]
    const float* nrm   = (const float*)d_in[2];   // [B,F,3,3]
    const float* cmp   = (const float*)d_in[3];   // [B,F,3,3]
    const int*   faces = (const int*)  d_in[4];   // [B,F,3]
    float* out = (float*)d_out;

    dim3 grid1(NPTS / (BLK * PPT), NSPLIT);       // (8, 64)
    p2m_search_kernel<<<grid1, BLK>>>(tri, pts);
    p2m_finalize_kernel<<<NPTS / 256, 256>>>(tri, pts, nrm, cmp, faces, out);
}

// round 12
// speedup vs baseline: 1.1366x; 1.1366x over previous
#include <cuda_runtime.h>
#include <cuda_bf16.h>
#include <math_constants.h>

#define BB      2
#define FF      8192
#define QQ      4096
#define NPTS    (BB * QQ)        // 8192
#define NSPLIT  64
#define FSEG    (FF / NSPLIT)    // 128
#define TILE    128              // == FSEG: single-tile blocks
#define BLK     128
#define PPT     4                // points per thread (2 f32x2 pairs)
#define NREC    11               // ulonglong2 per triangle record

typedef unsigned long long u64;

// Per-point argmin: stores ~key where key = (float_bits(d2)<<32) | fid.
// atomicMax(~key) == min(key); zero-init is the identity, so no init kernel.
// Finalize resets slots to 0 after reading (graph-replay deterministic).
// Smaller fid wins exact d2 ties = first-occurrence argmin.
__device__ u64 g_key[NPTS];   // static zero-init

// ---------------------------------------------------------------------------
// f32x2 packed helpers (sm_103a)
// ---------------------------------------------------------------------------
__device__ __forceinline__ u64 PK(float lo, float hi) {
    u64 r; asm("mov.b64 %0, {%1, %2};" : "=l"(r) : "f"(lo), "f"(hi)); return r;
}
__device__ __forceinline__ void UPK(u64 p, float& lo, float& hi) {
    asm("mov.b64 {%0, %1}, %2;" : "=f"(lo), "=f"(hi) : "l"(p));
}
__device__ __forceinline__ u64 FMA2(u64 a, u64 b, u64 c) {
    u64 d; asm("fma.rn.f32x2 %0, %1, %2, %3;" : "=l"(d) : "l"(a), "l"(b), "l"(c)); return d;
}
__device__ __forceinline__ u64 ADD2(u64 a, u64 b) {
    u64 d; asm("add.rn.f32x2 %0, %1, %2;" : "=l"(d) : "l"(a), "l"(b)); return d;
}
__device__ __forceinline__ u64 MUL2(u64 a, u64 b) {
    u64 d; asm("mul.rn.f32x2 %0, %1, %2;" : "=l"(d) : "l"(a), "l"(b)); return d;
}

__device__ __forceinline__ float clamp01(float t) {
    return fminf(fmaxf(t, 0.0f), 1.0f);
}
__device__ __forceinline__ u64 CLAMP01_2(u64 t) {
    float lo, hi; UPK(t, lo, hi);
    return PK(clamp01(lo), clamp01(hi));
}

// ---------------------------------------------------------------------------
// Exact reference arithmetic (finalize only — produces the actual outputs).
// ---------------------------------------------------------------------------
__device__ __forceinline__ float safe_div(float n, float d) {
    return n / ((d == 0.0f) ? 1.0f : d);
}

__device__ __forceinline__ void bary_uvw_exact(
    float ax, float ay, float az,
    float bx, float by, float bz,
    float cx, float cy, float cz,
    float px, float py, float pz,
    float& u, float& v, float& w)
{
    float abx = bx - ax, aby = by - ay, abz = bz - az;
    float acx = cx - ax, acy = cy - ay, acz = cz - az;
    float apx = px - ax, apy = py - ay, apz = pz - az;
    float d1 = abx * apx + aby * apy + abz * apz;
    float d2 = acx * apx + acy * apy + acz * apz;
    float bpx = px - bx, bpy = py - by, bpz = pz - bz;
    float d3 = abx * bpx + aby * bpy + abz * bpz;
    float d4 = acx * bpx + acy * bpy + acz * bpz;
    float cpx = px - cx, cpy = py - cy, cpz = pz - cz;
    float d5 = abx * cpx + aby * cpy + abz * cpz;
    float d6 = acx * cpx + acy * cpy + acz * cpz;
    float vc = d1 * d4 - d3 * d2;
    float vb = d5 * d2 - d1 * d6;
    float va = d3 * d6 - d5 * d4;

    float inv = safe_div(1.0f, va + vb + vc);
    v = vb * inv;
    w = vc * inv;

    if (va <= 0.0f && d4 >= d3 && d5 >= d6) {
        float num = d4 - d3;
        float wbc = safe_div(num, num + (d5 - d6));
        v = 1.0f - wbc; w = wbc;
    }
    if (vb <= 0.0f && d2 >= 0.0f && d6 <= 0.0f) {
        v = 0.0f; w = safe_div(d2, d2 - d6);
    }
    if (d6 >= 0.0f && d5 <= d6) { v = 0.0f; w = 1.0f; }
    if (vc <= 0.0f && d1 >= 0.0f && d3 <= 0.0f) {
        v = safe_div(d1, d1 - d3); w = 0.0f;
    }
    if (d3 >= 0.0f && d4 <= d3) { v = 1.0f; w = 0.0f; }
    if (d1 <= 0.0f && d2 <= 0.0f) { v = 0.0f; w = 0.0f; }

    u = 1.0f - v - w;
}

// ---------------------------------------------------------------------------
// Per-pair test macro (2 points packed in f32x2). Uses triangle record values
// L0..L10 from the enclosing scope. 2D-frame formulation:
// d^2 = h^2 + (inside ? 0 : min of three 2D segment distances).
// ---------------------------------------------------------------------------
#define TEST_PAIR(PX, PY, PZ, BEST0, BIDX0, BEST1, BIDX1)                     \
{                                                                             \
    u64 apx = ADD2(PX, L0.x), apy = ADD2(PY, L0.y), apz = ADD2(PZ, L1.x);     \
    u64 x = FMA2(L1.y, apx, FMA2(L2.x, apy, MUL2(L2.y, apz)));                \
    u64 y = FMA2(L3.x, apx, FMA2(L3.y, apy, MUL2(L4.x, apz)));                \
    u64 h = FMA2(L4.y, apx, FMA2(L5.x, apy, MUL2(L5.y, apz)));                \
    u64 xb = ADD2(x, L6.x);                                                   \
    float x0_, x1_, xb0_, xb1_;                                               \
    UPK(x, x0_, x1_); UPK(xb, xb0_, xb1_);                                    \
    u64 dxab = PK(fmaxf(xb0_, fminf(x0_, 0.0f)),                              \
                  fmaxf(xb1_, fminf(x1_, 0.0f)));                             \
    u64 dAB = FMA2(dxab, dxab, MUL2(y, y));                                   \
    u64 tca = CLAMP01_2(FMA2(x, L6.y, MUL2(y, L7.x)));                        \
    u64 dxc = FMA2(tca, L7.y, x);                                             \
    u64 dyc = FMA2(tca, L8.x, y);                                             \
    u64 dCA = FMA2(dxc, dxc, MUL2(dyc, dyc));                                 \
    u64 tbc = CLAMP01_2(FMA2(xb, L8.y, MUL2(y, L9.x)));                       \
    u64 dxb = FMA2(tbc, L9.y, xb);                                            \
    u64 dyb = FMA2(tbc, L8.x, y);                                             \
    u64 dBC = FMA2(dxb, dxb, MUL2(dyb, dyb));                                 \
    u64 s1 = FMA2(L10.y, x, MUL2(L7.y, y));                                   \
    u64 s2 = FMA2(L10.x, y, MUL2(L8.x, xb));                                  \
    float yy0_, yy1_, s10_, s11_, s20_, s21_;                                 \
    float dA0_, dA1_, dC0_, dC1_, dB0_, dB1_;                                 \
    UPK(y, yy0_, yy1_); UPK(s1, s10_, s11_); UPK(s2, s20_, s21_);             \
    UPK(dAB, dA0_, dA1_); UPK(dCA, dC0_, dC1_); UPK(dBC, dB0_, dB1_);         \
    float mn0_ = fminf(yy0_, fminf(s10_, s20_));                              \
    float mn1_ = fminf(yy1_, fminf(s11_, s21_));                              \
    float m0_ = (mn0_ >= 0.0f) ? 0.0f : fminf(fminf(dA0_, dC0_), dB0_);       \
    float m1_ = (mn1_ >= 0.0f) ? 0.0f : fminf(fminf(dA1_, dC1_), dB1_);       \
    u64 dist = FMA2(h, h, PK(m0_, m1_));                                      \
    float e0_, e1_; UPK(dist, e0_, e1_);                                      \
    if (e0_ < BEST0) { BEST0 = e0_; BIDX0 = fid; }                            \
    if (e1_ < BEST1) { BEST1 = e1_; BIDX1 = fid; }                            \
}

// ---------------------------------------------------------------------------
// Kernel 1: brute-force argmin search, 2D-frame, f32x2-packed, 4 pts/thread.
// grid = (NPTS/(BLK*PPT), NSPLIT) = (16, 64); one smem tile per block.
// smem record (22 packed-doubled u64 = 11 ulonglong2, 176 B/tri):
//   r0 (-ax,-ay)  r1 (-az,e1x)  r2 (e1y,e1z)  r3 (e2x,e2y)  r4 (e2z,nx)
//   r5 (ny,nz)    r6 (-b1,cs1)  r7 (cs2,-c1)  r8 (-c2,bcs1) r9 (bcs2,-bcx)
//   r10 (bcx,c2)
// ---------------------------------------------------------------------------
__global__ void __launch_bounds__(BLK, 4)
p2m_search_kernel(const float* __restrict__ tri, const float* __restrict__ pts)
{
    __shared__ ulonglong2 sT[TILE][NREC];

    const int tid = threadIdx.x;
    const int p0  = blockIdx.x * (BLK * PPT) + tid;
    const int p1  = p0 + BLK;               // all four in same batch:
    const int p2  = p0 + 2 * BLK;           // 512-aligned group, Q = 4096
    const int p3  = p0 + 3 * BLK;
    const int b   = p0 >> 12;
    const float* tb = tri + (size_t)b * FF * 9;

    const u64 pxA = PK(pts[p0 * 3 + 0], pts[p1 * 3 + 0]);
    const u64 pyA = PK(pts[p0 * 3 + 1], pts[p1 * 3 + 1]);
    const u64 pzA = PK(pts[p0 * 3 + 2], pts[p1 * 3 + 2]);
    const u64 pxB = PK(pts[p2 * 3 + 0], pts[p3 * 3 + 0]);
    const u64 pyB = PK(pts[p2 * 3 + 1], pts[p3 * 3 + 1]);
    const u64 pzB = PK(pts[p2 * 3 + 2], pts[p3 * 3 + 2]);

    const int f0 = blockIdx.y * FSEG;

    {   // one triangle per thread: build 2D frame record
        const float* s = tb + (size_t)(f0 + tid) * 9;
        float ax = s[0], ay = s[1], az = s[2];
        float bx = s[3], by = s[4], bz = s[5];
        float cx = s[6], cy = s[7], cz = s[8];
        float abx = bx - ax, aby = by - ay, abz = bz - az;
        float acx = cx - ax, acy = cy - ay, acz = cz - az;
        float abab = fmaf(abx, abx, fmaf(aby, aby, abz * abz));
        float acac = fmaf(acx, acx, fmaf(acy, acy, acz * acz));
        float abac = fmaf(abx, acx, fmaf(aby, acy, abz * acz));

        float rs1 = rsqrtf((abab == 0.0f) ? 1.0f : abab);
        float e1x = abx * rs1, e1y = aby * rs1, e1z = abz * rs1;
        float b1  = abab * rs1;                 // |ab|
        float c1  = abac * rs1;                 // ac . e1
        float qx = fmaf(-c1, e1x, acx);         // perp part of ac
        float qy = fmaf(-c1, e1y, acy);
        float qz = fmaf(-c1, e1z, acz);
        float qq = fmaf(qx, qx, fmaf(qy, qy, qz * qz));
        float rs2 = rsqrtf((qq == 0.0f) ? 1.0f : qq);
        float e2x = qx * rs2, e2y = qy * rs2, e2z = qz * rs2;
        float c2  = qq * rs2;                   // >= 0
        float nx = fmaf(e1y, e2z, -e1z * e2y);
        float ny = fmaf(e1z, e2x, -e1x * e2z);
        float nz = fmaf(e1x, e2y, -e1y * e2x);

        float invcc = 1.0f / ((acac == 0.0f) ? 1.0f : acac);
        float cs1 = c1 * invcc, cs2 = c2 * invcc;
        float bcx = c1 - b1;                    // 2D bc = (bcx, c2)
        float bcbc = fmaf(bcx, bcx, c2 * c2);
        float invbc = 1.0f / ((bcbc == 0.0f) ? 1.0f : bcbc);
        float bcs1 = bcx * invbc, bcs2 = c2 * invbc;

        ulonglong2* r = sT[tid];
        r[0]  = make_ulonglong2(PK(-ax, -ax),   PK(-ay, -ay));
        r[1]  = make_ulonglong2(PK(-az, -az),   PK(e1x, e1x));
        r[2]  = make_ulonglong2(PK(e1y, e1y),   PK(e1z, e1z));
        r[3]  = make_ulonglong2(PK(e2x, e2x),   PK(e2y, e2y));
        r[4]  = make_ulonglong2(PK(e2z, e2z),   PK(nx, nx));
        r[5]  = make_ulonglong2(PK(ny, ny),     PK(nz, nz));
        r[6]  = make_ulonglong2(PK(-b1, -b1),   PK(cs1, cs1));
        r[7]  = make_ulonglong2(PK(cs2, cs2),   PK(-c1, -c1));
        r[8]  = make_ulonglong2(PK(-c2, -c2),   PK(bcs1, bcs1));
        r[9]  = make_ulonglong2(PK(bcs2, bcs2), PK(-bcx, -bcx));
        r[10] = make_ulonglong2(PK(bcx, bcx),   PK(c2, c2));
    }
    __syncthreads();

    float bestA0 = CUDART_INF_F, bestA1 = CUDART_INF_F;
    float bestB0 = CUDART_INF_F, bestB1 = CUDART_INF_F;
    int   bidxA0 = f0, bidxA1 = f0, bidxB0 = f0, bidxB1 = f0;

    #pragma unroll 2
    for (int j = 0; j < TILE; ++j) {
        const ulonglong2* r = sT[j];
        const ulonglong2 L0 = r[0], L1 = r[1], L2 = r[2], L3 = r[3];
        const ulonglong2 L4 = r[4], L5 = r[5], L6 = r[6], L7 = r[7];
        const ulonglong2 L8 = r[8], L9 = r[9], L10 = r[10];
        const int fid = f0 + j;

        TEST_PAIR(pxA, pyA, pzA, bestA0, bidxA0, bestA1, bidxA1);
        TEST_PAIR(pxB, pyB, pzB, bestB0, bidxB0, bestB1, bidxB1);
    }

    u64 kA0 = ((u64)__float_as_uint(bestA0) << 32) | (u64)(unsigned)bidxA0;
    u64 kA1 = ((u64)__float_as_uint(bestA1) << 32) | (u64)(unsigned)bidxA1;
    u64 kB0 = ((u64)__float_as_uint(bestB0) << 32) | (u64)(unsigned)bidxB0;
    u64 kB1 = ((u64)__float_as_uint(bestB1) << 32) | (u64)(unsigned)bidxB1;
    atomicMax(&g_key[p0], ~kA0);
    atomicMax(&g_key[p1], ~kA1);
    atomicMax(&g_key[p2], ~kB0);
    atomicMax(&g_key[p3], ~kB1);
}

// ---------------------------------------------------------------------------
// Kernel 2: read winning triangle (complemented key), reset slot for next
// graph replay, recompute exact reference bary, clamp, gather, write outputs.
// Launched 64 blocks x 128 threads to spread latency-bound gathers over more
// SMs (was 32x256 -> only 32 SMs busy).
// Output (float32): residual[8192*3] | normals[8192*3] | cmaps[8192*3] | idx[8192]
// ---------------------------------------------------------------------------
__global__ void p2m_finalize_kernel(
    const float* __restrict__ tri, const float* __restrict__ pts,
    const float* __restrict__ nrm, const float* __restrict__ cmp,
    const int*   __restrict__ faces, float* __restrict__ out)
{
    const int pid = blockIdx.x * blockDim.x + threadIdx.x;
    if (pid >= NPTS) return;

    const u64 raw = g_key[pid];
    g_key[pid] = 0ull;                         // reset for next replay
    const int bidx = (int)((~raw) & 0xFFFFFFFFull);

    const int b = pid >> 12;
    const size_t fbase = (size_t)(b * FF + bidx);

    const float px = pts[pid * 3 + 0];
    const float py = pts[pid * 3 + 1];
    const float pz = pts[pid * 3 + 2];

    const float* t = tri + fbase * 9;
    float ax = t[0], ay = t[1], az = t[2];
    float bx = t[3], by = t[4], bz = t[5];
    float cx = t[6], cy = t[7], cz = t[8];

    float u, v, w;
    bary_uvw_exact(ax, ay, az, bx, by, bz, cx, cy, cz, px, py, pz, u, v, w);

    u = fminf(fmaxf(u, 0.0f), 1.0f);
    v = fminf(fmaxf(v, 0.0f), 1.0f);
    w = fminf(fmaxf(w, 0.0f), 1.0f);

    out[pid * 3 + 0] = (u * ax + v * bx + w * cx) - px;
    out[pid * 3 + 1] = (u * ay + v * by + w * cy) - py;
    out[pid * 3 + 2] = (u * az + v * bz + w * cz) - pz;

    const float* n = nrm + fbase * 9;
    out[NPTS * 3 + pid * 3 + 0] = u * n[0] + v * n[3] + w * n[6];
    out[NPTS * 3 + pid * 3 + 1] = u * n[1] + v * n[4] + w * n[7];
    out[NPTS * 3 + pid * 3 + 2] = u * n[2] + v * n[5] + w * n[8];

    const float* cm = cmp + fbase * 9;
    out[NPTS * 6 + pid * 3 + 0] = u * cm[0] + v * cm[3] + w * cm[6];
    out[NPTS * 6 + pid * 3 + 1] = u * cm[1] + v * cm[4] + w * cm[7];
    out[NPTS * 6 + pid * 3 + 2] = u * cm[2] + v * cm[5] + w * cm[8];

    int k = (u >= v && u >= w) ? 0 : ((v >= w) ? 1 : 2);
    out[NPTS * 9 + pid] = (float)faces[fbase * 3 + k];
}

extern "C" void kernel_launch(void* const* d_in, const int* in_sizes, int n_in,
                              void* d_out, int out_size)
{
    const float* tri   = (const float*)d_in[0];   // [B,F,3,3]
    const float* pts   = (const float*)d_in[1];   // [B,Q,3]
    const float* nrm   = (const float*)d_in[2];   // [B,F,3,3]
    const float* cmp   = (const float*)d_in[3];   // [B,F,3,3]
    const int*   faces = (const int*)  d_in[4];   // [B,F,3]
    float* out = (float*)d_out;

    dim3 grid1(NPTS / (BLK * PPT), NSPLIT);       // (16, 64)
    p2m_search_kernel<<<grid1, BLK>>>(tri, pts);
    p2m_finalize_kernel<<<NPTS / 128, 128>>>(tri, pts, nrm, cmp, faces, out);
}

// round 13
// speedup vs baseline: 1.1369x; 1.0003x over previous
#include <cuda_runtime.h>
#include <cuda_bf16.h>
#include <math_constants.h>

#define BB      2
#define FF      8192
#define QQ      4096
#define NPTS    (BB * QQ)        // 8192
#define NSPLIT  64
#define FSEG    (FF / NSPLIT)    // 128
#define TILE    128              // == FSEG: single-tile blocks
#define BLK     128
#define PPT     4                // points per thread (2 f32x2 pairs)
#define NREC    11               // ulonglong2 per triangle record

typedef unsigned long long u64;

// Per-point argmin: stores ~key where key = (float_bits(d2)<<32) | fid.
// atomicMax(~key) == min(key); zero-init is the identity, so no init kernel.
// Finalize resets slots to 0 after reading (graph-replay deterministic).
// Smaller fid wins exact d2 ties = first-occurrence argmin.
__device__ u64 g_key[NPTS];   // static zero-init

// ---------------------------------------------------------------------------
// f32x2 packed helpers (sm_103a)
// ---------------------------------------------------------------------------
__device__ __forceinline__ u64 PK(float lo, float hi) {
    u64 r; asm("mov.b64 %0, {%1, %2};" : "=l"(r) : "f"(lo), "f"(hi)); return r;
}
__device__ __forceinline__ void UPK(u64 p, float& lo, float& hi) {
    asm("mov.b64 {%0, %1}, %2;" : "=f"(lo), "=f"(hi) : "l"(p));
}
__device__ __forceinline__ u64 FMA2(u64 a, u64 b, u64 c) {
    u64 d; asm("fma.rn.f32x2 %0, %1, %2, %3;" : "=l"(d) : "l"(a), "l"(b), "l"(c)); return d;
}
__device__ __forceinline__ u64 ADD2(u64 a, u64 b) {
    u64 d; asm("add.rn.f32x2 %0, %1, %2;" : "=l"(d) : "l"(a), "l"(b)); return d;
}
__device__ __forceinline__ u64 MUL2(u64 a, u64 b) {
    u64 d; asm("mul.rn.f32x2 %0, %1, %2;" : "=l"(d) : "l"(a), "l"(b)); return d;
}

__device__ __forceinline__ float clamp01(float t) {
    return fminf(fmaxf(t, 0.0f), 1.0f);
}
__device__ __forceinline__ u64 CLAMP01_2(u64 t) {
    float lo, hi; UPK(t, lo, hi);
    return PK(clamp01(lo), clamp01(hi));
}

// ---------------------------------------------------------------------------
// Exact reference arithmetic (finalize only — produces the actual outputs).
// ---------------------------------------------------------------------------
__device__ __forceinline__ float safe_div(float n, float d) {
    return n / ((d == 0.0f) ? 1.0f : d);
}

__device__ __forceinline__ void bary_uvw_exact(
    float ax, float ay, float az,
    float bx, float by, float bz,
    float cx, float cy, float cz,
    float px, float py, float pz,
    float& u, float& v, float& w)
{
    float abx = bx - ax, aby = by - ay, abz = bz - az;
    float acx = cx - ax, acy = cy - ay, acz = cz - az;
    float apx = px - ax, apy = py - ay, apz = pz - az;
    float d1 = abx * apx + aby * apy + abz * apz;
    float d2 = acx * apx + acy * apy + acz * apz;
    float bpx = px - bx, bpy = py - by, bpz = pz - bz;
    float d3 = abx * bpx + aby * bpy + abz * bpz;
    float d4 = acx * bpx + acy * bpy + acz * bpz;
    float cpx = px - cx, cpy = py - cy, cpz = pz - cz;
    float d5 = abx * cpx + aby * cpy + abz * cpz;
    float d6 = acx * cpx + acy * cpy + acz * cpz;
    float vc = d1 * d4 - d3 * d2;
    float vb = d5 * d2 - d1 * d6;
    float va = d3 * d6 - d5 * d4;

    float inv = safe_div(1.0f, va + vb + vc);
    v = vb * inv;
    w = vc * inv;

    if (va <= 0.0f && d4 >= d3 && d5 >= d6) {
        float num = d4 - d3;
        float wbc = safe_div(num, num + (d5 - d6));
        v = 1.0f - wbc; w = wbc;
    }
    if (vb <= 0.0f && d2 >= 0.0f && d6 <= 0.0f) {
        v = 0.0f; w = safe_div(d2, d2 - d6);
    }
    if (d6 >= 0.0f && d5 <= d6) { v = 0.0f; w = 1.0f; }
    if (vc <= 0.0f && d1 >= 0.0f && d3 <= 0.0f) {
        v = safe_div(d1, d1 - d3); w = 0.0f;
    }
    if (d3 >= 0.0f && d4 <= d3) { v = 1.0f; w = 0.0f; }
    if (d1 <= 0.0f && d2 <= 0.0f) { v = 0.0f; w = 0.0f; }

    u = 1.0f - v - w;
}

// ---------------------------------------------------------------------------
// Per-pair test macro (2 points packed in f32x2). Uses triangle record values
// L0..L10 from the enclosing scope. 2D-frame formulation:
// d^2 = h^2 + (inside ? 0 : min of three 2D segment distances).
// ---------------------------------------------------------------------------
#define TEST_PAIR(PX, PY, PZ, BEST0, BIDX0, BEST1, BIDX1)                     \
{                                                                             \
    u64 apx = ADD2(PX, L0.x), apy = ADD2(PY, L0.y), apz = ADD2(PZ, L1.x);     \
    u64 x = FMA2(L1.y, apx, FMA2(L2.x, apy, MUL2(L2.y, apz)));                \
    u64 y = FMA2(L3.x, apx, FMA2(L3.y, apy, MUL2(L4.x, apz)));                \
    u64 h = FMA2(L4.y, apx, FMA2(L5.x, apy, MUL2(L5.y, apz)));                \
    u64 xb = ADD2(x, L6.x);                                                   \
    float x0_, x1_, xb0_, xb1_;                                               \
    UPK(x, x0_, x1_); UPK(xb, xb0_, xb1_);                                    \
    u64 dxab = PK(fmaxf(xb0_, fminf(x0_, 0.0f)),                              \
                  fmaxf(xb1_, fminf(x1_, 0.0f)));                             \
    u64 dAB = FMA2(dxab, dxab, MUL2(y, y));                                   \
    u64 tca = CLAMP01_2(FMA2(x, L6.y, MUL2(y, L7.x)));                        \
    u64 dxc = FMA2(tca, L7.y, x);                                             \
    u64 dyc = FMA2(tca, L8.x, y);                                             \
    u64 dCA = FMA2(dxc, dxc, MUL2(dyc, dyc));                                 \
    u64 tbc = CLAMP01_2(FMA2(xb, L8.y, MUL2(y, L9.x)));                       \
    u64 dxb = FMA2(tbc, L9.y, xb);                                            \
    u64 dyb = FMA2(tbc, L8.x, y);                                             \
    u64 dBC = FMA2(dxb, dxb, MUL2(dyb, dyb));                                 \
    u64 s1 = FMA2(L10.y, x, MUL2(L7.y, y));                                   \
    u64 s2 = FMA2(L10.x, y, MUL2(L8.x, xb));                                  \
    float yy0_, yy1_, s10_, s11_, s20_, s21_;                                 \
    float dA0_, dA1_, dC0_, dC1_, dB0_, dB1_;                                 \
    UPK(y, yy0_, yy1_); UPK(s1, s10_, s11_); UPK(s2, s20_, s21_);             \
    UPK(dAB, dA0_, dA1_); UPK(dCA, dC0_, dC1_); UPK(dBC, dB0_, dB1_);         \
    float mn0_ = fminf(yy0_, fminf(s10_, s20_));                              \
    float mn1_ = fminf(yy1_, fminf(s11_, s21_));                              \
    float m0_ = (mn0_ >= 0.0f) ? 0.0f : fminf(fminf(dA0_, dC0_), dB0_);       \
    float m1_ = (mn1_ >= 0.0f) ? 0.0f : fminf(fminf(dA1_, dC1_), dB1_);       \
    u64 dist = FMA2(h, h, PK(m0_, m1_));                                      \
    float e0_, e1_; UPK(dist, e0_, e1_);                                      \
    if (e0_ < BEST0) { BEST0 = e0_; BIDX0 = fid; }                            \
    if (e1_ < BEST1) { BEST1 = e1_; BIDX1 = fid; }                            \
}

// ---------------------------------------------------------------------------
// Kernel 1: brute-force argmin search, 2D-frame, f32x2-packed, 4 pts/thread.
// grid = (NPTS/(BLK*PPT), NSPLIT) = (16, 64); one smem tile per block.
// unroll 4: 8 independent dependency chains in flight per warp to lift
// fma-pipe utilization from the measured ~76%.
// smem record (22 packed-doubled u64 = 11 ulonglong2, 176 B/tri):
//   r0 (-ax,-ay)  r1 (-az,e1x)  r2 (e1y,e1z)  r3 (e2x,e2y)  r4 (e2z,nx)
//   r5 (ny,nz)    r6 (-b1,cs1)  r7 (cs2,-c1)  r8 (-c2,bcs1) r9 (bcs2,-bcx)
//   r10 (bcx,c2)
// ---------------------------------------------------------------------------
__global__ void __launch_bounds__(BLK, 4)
p2m_search_kernel(const float* __restrict__ tri, const float* __restrict__ pts)
{
    __shared__ ulonglong2 sT[TILE][NREC];

    const int tid = threadIdx.x;
    const int p0  = blockIdx.x * (BLK * PPT) + tid;
    const int p1  = p0 + BLK;               // all four in same batch:
    const int p2  = p0 + 2 * BLK;           // 512-aligned group, Q = 4096
    const int p3  = p0 + 3 * BLK;
    const int b   = p0 >> 12;
    const float* tb = tri + (size_t)b * FF * 9;

    const u64 pxA = PK(pts[p0 * 3 + 0], pts[p1 * 3 + 0]);
    const u64 pyA = PK(pts[p0 * 3 + 1], pts[p1 * 3 + 1]);
    const u64 pzA = PK(pts[p0 * 3 + 2], pts[p1 * 3 + 2]);
    const u64 pxB = PK(pts[p2 * 3 + 0], pts[p3 * 3 + 0]);
    const u64 pyB = PK(pts[p2 * 3 + 1], pts[p3 * 3 + 1]);
    const u64 pzB = PK(pts[p2 * 3 + 2], pts[p3 * 3 + 2]);

    const int f0 = blockIdx.y * FSEG;

    {   // one triangle per thread: build 2D frame record
        const float* s = tb + (size_t)(f0 + tid) * 9;
        float ax = s[0], ay = s[1], az = s[2];
        float bx = s[3], by = s[4], bz = s[5];
        float cx = s[6], cy = s[7], cz = s[8];
        float abx = bx - ax, aby = by - ay, abz = bz - az;
        float acx = cx - ax, acy = cy - ay, acz = cz - az;
        float abab = fmaf(abx, abx, fmaf(aby, aby, abz * abz));
        float acac = fmaf(acx, acx, fmaf(acy, acy, acz * acz));
        float abac = fmaf(abx, acx, fmaf(aby, acy, abz * acz));

        float rs1 = rsqrtf((abab == 0.0f) ? 1.0f : abab);
        float e1x = abx * rs1, e1y = aby * rs1, e1z = abz * rs1;
        float b1  = abab * rs1;                 // |ab|
        float c1  = abac * rs1;                 // ac . e1
        float qx = fmaf(-c1, e1x, acx);         // perp part of ac
        float qy = fmaf(-c1, e1y, acy);
        float qz = fmaf(-c1, e1z, acz);
        float qq = fmaf(qx, qx, fmaf(qy, qy, qz * qz));
        float rs2 = rsqrtf((qq == 0.0f) ? 1.0f : qq);
        float e2x = qx * rs2, e2y = qy * rs2, e2z = qz * rs2;
        float c2  = qq * rs2;                   // >= 0
        float nx = fmaf(e1y, e2z, -e1z * e2y);
        float ny = fmaf(e1z, e2x, -e1x * e2z);
        float nz = fmaf(e1x, e2y, -e1y * e2x);

        float invcc = 1.0f / ((acac == 0.0f) ? 1.0f : acac);
        float cs1 = c1 * invcc, cs2 = c2 * invcc;
        float bcx = c1 - b1;                    // 2D bc = (bcx, c2)
        float bcbc = fmaf(bcx, bcx, c2 * c2);
        float invbc = 1.0f / ((bcbc == 0.0f) ? 1.0f : bcbc);
        float bcs1 = bcx * invbc, bcs2 = c2 * invbc;

        ulonglong2* r = sT[tid];
        r[0]  = make_ulonglong2(PK(-ax, -ax),   PK(-ay, -ay));
        r[1]  = make_ulonglong2(PK(-az, -az),   PK(e1x, e1x));
        r[2]  = make_ulonglong2(PK(e1y, e1y),   PK(e1z, e1z));
        r[3]  = make_ulonglong2(PK(e2x, e2x),   PK(e2y, e2y));
        r[4]  = make_ulonglong2(PK(e2z, e2z),   PK(nx, nx));
        r[5]  = make_ulonglong2(PK(ny, ny),     PK(nz, nz));
        r[6]  = make_ulonglong2(PK(-b1, -b1),   PK(cs1, cs1));
        r[7]  = make_ulonglong2(PK(cs2, cs2),   PK(-c1, -c1));
        r[8]  = make_ulonglong2(PK(-c2, -c2),   PK(bcs1, bcs1));
        r[9]  = make_ulonglong2(PK(bcs2, bcs2), PK(-bcx, -bcx));
        r[10] = make_ulonglong2(PK(bcx, bcx),   PK(c2, c2));
    }
    __syncthreads();

    float bestA0 = CUDART_INF_F, bestA1 = CUDART_INF_F;
    float bestB0 = CUDART_INF_F, bestB1 = CUDART_INF_F;
    int   bidxA0 = f0, bidxA1 = f0, bidxB0 = f0, bidxB1 = f0;

    #pragma unroll 4
    for (int j = 0; j < TILE; ++j) {
        const ulonglong2* r = sT[j];
        const ulonglong2 L0 = r[0], L1 = r[1], L2 = r[2], L3 = r[3];
        const ulonglong2 L4 = r[4], L5 = r[5], L6 = r[6], L7 = r[7];
        const ulonglong2 L8 = r[8], L9 = r[9], L10 = r[10];
        const int fid = f0 + j;

        TEST_PAIR(pxA, pyA, pzA, bestA0, bidxA0, bestA1, bidxA1);
        TEST_PAIR(pxB, pyB, pzB, bestB0, bidxB0, bestB1, bidxB1);
    }

    u64 kA0 = ((u64)__float_as_uint(bestA0) << 32) | (u64)(unsigned)bidxA0;
    u64 kA1 = ((u64)__float_as_uint(bestA1) << 32) | (u64)(unsigned)bidxA1;
    u64 kB0 = ((u64)__float_as_uint(bestB0) << 32) | (u64)(unsigned)bidxB0;
    u64 kB1 = ((u64)__float_as_uint(bestB1) << 32) | (u64)(unsigned)bidxB1;
    atomicMax(&g_key[p0], ~kA0);
    atomicMax(&g_key[p1], ~kA1);
    atomicMax(&g_key[p2], ~kB0);
    atomicMax(&g_key[p3], ~kB1);
}

// ---------------------------------------------------------------------------
// Kernel 2: read winning triangle (complemented key), reset slot for next
// graph replay, recompute exact reference bary, clamp, gather, write outputs.
// Output (float32): residual[8192*3] | normals[8192*3] | cmaps[8192*3] | idx[8192]
// ---------------------------------------------------------------------------
__global__ void p2m_finalize_kernel(
    const float* __restrict__ tri, const float* __restrict__ pts,
    const float* __restrict__ nrm, const float* __restrict__ cmp,
    const int*   __restrict__ faces, float* __restrict__ out)
{
    const int pid = blockIdx.x * blockDim.x + threadIdx.x;
    if (pid >= NPTS) return;

    const u64 raw = g_key[pid];
    g_key[pid] = 0ull;                         // reset for next replay
    const int bidx = (int)((~raw) & 0xFFFFFFFFull);

    const int b = pid >> 12;
    const size_t fbase = (size_t)(b * FF + bidx);

    const float px = pts[pid * 3 + 0];
    const float py = pts[pid * 3 + 1];
    const float pz = pts[pid * 3 + 2];

    const float* t = tri + fbase * 9;
    float ax = t[0], ay = t[1], az = t[2];
    float bx = t[3], by = t[4], bz = t[5];
    float cx = t[6], cy = t[7], cz = t[8];

    float u, v, w;
    bary_uvw_exact(ax, ay, az, bx, by, bz, cx, cy, cz, px, py, pz, u, v, w);

    u = fminf(fmaxf(u, 0.0f), 1.0f);
    v = fminf(fmaxf(v, 0.0f), 1.0f);
    w = fminf(fmaxf(w, 0.0f), 1.0f);

    out[pid * 3 + 0] = (u * ax + v * bx + w * cx) - px;
    out[pid * 3 + 1] = (u * ay + v * by + w * cy) - py;
    out[pid * 3 + 2] = (u * az + v * bz + w * cz) - pz;

    const float* n = nrm + fbase * 9;
    out[NPTS * 3 + pid * 3 + 0] = u * n[0] + v * n[3] + w * n[6];
    out[NPTS * 3 + pid * 3 + 1] = u * n[1] + v * n[4] + w * n[7];
    out[NPTS * 3 + pid * 3 + 2] = u * n[2] + v * n[5] + w * n[8];

    const float* cm = cmp + fbase * 9;
    out[NPTS * 6 + pid * 3 + 0] = u * cm[0] + v * cm[3] + w * cm[6];
    out[NPTS * 6 + pid * 3 + 1] = u * cm[1] + v * cm[4] + w * cm[7];
    out[NPTS * 6 + pid * 3 + 2] = u * cm[2] + v * cm[5] + w * cm[8];

    int k = (u >= v && u >= w) ? 0 : ((v >= w) ? 1 : 2);
    out[NPTS * 9 + pid] = (float)faces[fbase * 3 + k];
}

extern "C" void kernel_launch(void* const* d_in, const int* in_sizes, int n_in,
                              void* d_out, int out_size)
{
    const float* tri   = (const float*)d_in[0];   // [B,F,3,3]
    const float* pts   = (const float*)d_in[1];   // [B,Q,3]
    const float* nrm   = (const float*)d_in[2];   // [B,F,3,3]
    const float* cmp   = (const float*)d_in[3];   // [B,F,3,3]
    const int*   faces = (const int*)  d_in[4];   // [B,F,3]
    float* out = (float*)d_out;

    dim3 grid1(NPTS / (BLK * PPT), NSPLIT);       // (16, 64)
    p2m_search_kernel<<<grid1, BLK>>>(tri, pts);
    p2m_finalize_kernel<<<NPTS / 128, 128>>>(tri, pts, nrm, cmp, faces, out);
}